// round 12
// baseline (speedup 1.0000x reference)
#include <cuda_runtime.h>
#include <cuda_fp16.h>
#include <cstdint>

// NSSTDecomposition via fp16 m16n8k16 mma.sync, per-scale implicit-GEMM split.
// s2: K=19x20(pad)=384, N=16 ; s1: K=15x16=240, N=8 ; s0: K=11x12->144, N=8.
// R10: fix R9 OOB — K-pad tail reads dy=19 (s2), so window needs
// roff+row_w+dy = 0+7+19 = 26 -> WROWS=27 rows. Rest of R9 design unchanged:
// 8 y-rows per CTA (warp = 1 row x 128 px = 8 m16 tiles), fused lowpass.

#define IMG_W   512
#define IMG_HW  (512*512)
#define WROWS   27             // 8 rows + 2*9 halo + 1 K-pad overread row
#define WCOLS   152
#define WELEMS  (WROWS*WCOLS)  // 4104

// fragment slots per color: s2: 24g*2nt=48, s1: 15, s0: 9  => 72
#define SLOTS   72
#define SLOT_S1 48
#define SLOT_S0 63

__device__ uint2 g_bfrag[3*SLOTS*32];

__device__ __forceinline__ void mma_f16(float* d,
    uint32_t a0, uint32_t a1, uint32_t a2, uint32_t a3, uint32_t b0, uint32_t b1) {
    asm volatile("mma.sync.aligned.m16n8k16.row.col.f32.f16.f16.f32 "
                 "{%0,%1,%2,%3}, {%4,%5,%6,%7}, {%8,%9}, {%0,%1,%2,%3};"
                 : "+f"(d[0]), "+f"(d[1]), "+f"(d[2]), "+f"(d[3])
                 : "r"(a0), "r"(a1), "r"(a2), "r"(a3), "r"(b0), "r"(b1));
}

// ---------------------------------------------------------------------------
// Prep: weights -> f16 fragment image. Lane l of slot: n_row=l>>2, k pair base
// kq=(l&3)*2 ; b0 = {W[n][k0],W[n][k0+1]}, b1 = {W[n][k0+8],W[n][k0+9]}.
// ---------------------------------------------------------------------------
__global__ void __launch_bounds__(256)
nsst_prep(const float* __restrict__ f0, const float* __restrict__ f1,
          const float* __restrict__ f2)
{
    int i = blockIdx.x * 256 + threadIdx.x;          // 3*72*32 = 6912
    if (i >= 3 * SLOTS * 32) return;
    int l    = i & 31;
    int slot = (i >> 5) % SLOTS;
    int c    = i / (SLOTS * 32);
    int nr   = l >> 2;
    int kq   = (l & 3) * 2;

    uint32_t pk[2];
    #pragma unroll
    for (int r = 0; r < 2; r++) {
        int g, k;
        float v0 = 0.0f, v1 = 0.0f;
        if (slot < SLOT_S1) {                         // scale2: 19x19, PADW=20
            g = slot >> 1;
            int nt = slot & 1, nl = nt * 8 + nr;
            k = g * 16 + kq + r * 8;
            int dy = k / 20, dx = k - dy * 20;
            if (dy < 19 && nl < 16) {
                const float* fp = f2 + (size_t)(c * 16 + nl) * 361 + dy * 19 + dx;
                if (dx < 19)     v0 = fp[0];
                if (dx + 1 < 19) v1 = fp[1];
            }
        } else if (slot < SLOT_S0) {                  // scale1: 15x15, PADW=16
            g = slot - SLOT_S1;
            k = g * 16 + kq + r * 8;
            int dy = k >> 4, dx = k & 15;
            const float* fp = f1 + (size_t)(c * 8 + nr) * 225 + dy * 15 + dx;
            if (dx < 15)     v0 = fp[0];
            if (dx + 1 < 15) v1 = fp[1];
        } else {                                      // scale0: 11x11, PADW=12
            g = slot - SLOT_S0;
            k = g * 16 + kq + r * 8;
            int dy = k / 12, dx = k - dy * 12;
            if (dy < 11 && nr < 4) {
                const float* fp = f0 + (size_t)(c * 4 + nr) * 121 + dy * 11 + dx;
                if (dx < 11)     v0 = fp[0];
                if (dx + 1 < 11) v1 = fp[1];
            }
        }
        __half2 hh = __halves2half2(__float2half_rn(v0), __float2half_rn(v1));
        pk[r] = *reinterpret_cast<uint32_t*>(&hh);
    }
    g_bfrag[i] = make_uint2(pk[0], pk[1]);
}

// ---------------------------------------------------------------------------
// One scale: NG groups of k16, NT n8-tiles, 8 m16-tiles per warp (128 px row).
// ---------------------------------------------------------------------------
template<int PADW, int RS, int NT, int NG, int NREAL, int CH0>
__device__ __forceinline__ void run_scale(
    const uint2* __restrict__ sb, const char* __restrict__ abase,
    float* __restrict__ obase,          // out + chbase*HW + y*512
    int l, int row_w, int x0)
{
    const int roff = 9 - RS;
    const int px   = l >> 2;
    const int kq   = (l & 3) * 2;

    float acc[8][NT][4];
    #pragma unroll
    for (int mt = 0; mt < 8; mt++)
        #pragma unroll
        for (int nt = 0; nt < NT; nt++)
            #pragma unroll
            for (int q = 0; q < 4; q++) acc[mt][nt][q] = 0.0f;

    #pragma unroll 1
    for (int g = 0; g < NG; g++) {
        int k0 = g * 16 + kq;
        int k1 = k0 + 8;
        int dy0 = k0 / PADW, dx0 = k0 - dy0 * PADW;
        int dy1 = k1 / PADW, dx1 = k1 - dy1 * PADW;
        int e0 = (roff + row_w + dy0) * WCOLS + roff + px + dx0;
        int e1 = (roff + row_w + dy1) * WCOLS + roff + px + dx1;

        uint2 bf[NT];
        #pragma unroll
        for (int nt = 0; nt < NT; nt++) bf[nt] = sb[(g * NT + nt) * 32 + l];

        #pragma unroll
        for (int mt = 0; mt < 8; mt++) {
            uint32_t a0 = *(const uint32_t*)(abase + (size_t)(e0 + mt * 16) * 2);
            uint32_t a1 = *(const uint32_t*)(abase + (size_t)(e0 + mt * 16 + 8) * 2);
            uint32_t a2 = *(const uint32_t*)(abase + (size_t)(e1 + mt * 16) * 2);
            uint32_t a3 = *(const uint32_t*)(abase + (size_t)(e1 + mt * 16 + 8) * 2);
            #pragma unroll
            for (int nt = 0; nt < NT; nt++)
                mma_f16(acc[mt][nt], a0, a1, a2, a3, bf[nt].x, bf[nt].y);
        }
    }

    const int n2 = kq;                    // (l&3)*2
    #pragma unroll
    for (int mt = 0; mt < 8; mt++) {
        int x = mt * 16 + px + x0;
        #pragma unroll
        for (int nt = 0; nt < NT; nt++) {
            int n = nt * 8 + n2;
            if (n < NREAL) {
                float* o = obase + (size_t)(CH0 + n) * IMG_HW;
                o[x]              = acc[mt][nt][0];
                o[IMG_HW + x]     = acc[mt][nt][1];
                o[x + 8]          = acc[mt][nt][2];
                o[IMG_HW + x + 8] = acc[mt][nt][3];
            }
        }
    }
}

// ---------------------------------------------------------------------------
// Conv: grid (4 x-tiles, 64 y-octets, 12 bc), 256 threads = 8 warps.
// Warp w = y-row w of the octet; covers 128 px x all dirs.
// ---------------------------------------------------------------------------
__global__ void __launch_bounds__(256, 2)
nsst_mma_conv(const float* __restrict__ img, float* __restrict__ out)
{
    __shared__ uint2 s_b[SLOTS * 32];                         // 18432 B
    __shared__ __align__(16) __half s_winA[WELEMS];           //  8208 B
    __shared__ __align__(16) __half s_winB[WELEMS];           //  8208 B (shift-1)

    const int tid = threadIdx.x;
    const int l   = tid & 31;
    const int w   = tid >> 5;
    const int x0  = blockIdx.x * 128;
    const int y0  = blockIdx.y * 8;
    const int bz  = blockIdx.z, b = bz / 3, c = bz % 3;

    // stage B fragments
    {
        const uint2* src = g_bfrag + (size_t)c * SLOTS * 32;
        for (int i = tid; i < SLOTS * 32; i += 256) s_b[i] = src[i];
    }
    // stage window (f16) + shifted copy, zero-padded
    {
        const float* src = img + (size_t)bz * IMG_HW;
        for (int i = tid; i < WELEMS; i += 256) {
            int iy = i / WCOLS, ix = i - iy * WCOLS;
            int gy = y0 + iy - 9, gx = x0 + ix - 9;
            float v = 0.0f;
            if ((unsigned)gy < 512u && (unsigned)gx < 512u) v = src[gy * IMG_W + gx];
            __half h = __float2half_rn(v);
            s_winA[i] = h;
            if (i > 0) s_winB[i - 1] = h;
        }
        if (tid == 0) s_winB[WELEMS - 1] = __float2half_rn(0.0f);
    }
    __syncthreads();

    const char* abase = ((l >> 2) & 1) ? ((const char*)s_winB - 2)
                                       : (const char*)s_winA;
    float* obase = out + (size_t)(b * 87 + c * 29) * IMG_HW
                       + (size_t)(y0 + w) * IMG_W;

    run_scale<20, 9, 2, 24, 16, 12>(s_b,                abase, obase, l, w, x0);
    run_scale<16, 7, 1, 15,  8,  4>(s_b + SLOT_S1 * 32, abase, obase, l, w, x0);
    run_scale<12, 5, 1,  9,  4,  0>(s_b + SLOT_S0 * 32, abase, obase, l, w, x0);
}

// ---------------------------------------------------------------------------
// Fused lowpass: 4x4 box mean + bilinear upsample (clamp == jax renorm edge).
// Block = 64x64 output region; 18x18 lowpass cells in smem.
// ---------------------------------------------------------------------------
__global__ void __launch_bounds__(256)
nsst_lowpass(const float* __restrict__ img, float* __restrict__ out)
{
    __shared__ float s_cell[18 * 18];
    const int tid = threadIdx.x;
    const int x0 = blockIdx.x * 64;
    const int y0 = blockIdx.y * 64;
    const int bz = blockIdx.z, b = bz / 3, c = bz % 3;
    const int cyb = (y0 >> 2) - 1;
    const int cxb = (x0 >> 2) - 1;
    const float* src = img + (size_t)bz * IMG_HW;

    for (int i = tid; i < 324; i += 256) {
        int cy = min(127, max(0, cyb + i / 18));
        int cx = min(127, max(0, cxb + i % 18));
        const float* p = src + (size_t)(cy * 4) * IMG_W + cx * 4;
        float s = 0.0f;
        #pragma unroll
        for (int r = 0; r < 4; r++) {
            float4 v = *reinterpret_cast<const float4*>(p + r * IMG_W);
            s += v.x + v.y + v.z + v.w;
        }
        s_cell[i] = s * (1.0f / 16.0f);
    }
    __syncthreads();

    float* o = out + (size_t)(b * 87 + c * 29 + 28) * IMG_HW;
    #pragma unroll
    for (int j = 0; j < 16; j++) {
        int idx = tid + j * 256;                 // 0..4095
        int oy = y0 + (idx >> 6);
        int ox = x0 + (idx & 63);
        float sy = oy * 0.25f - 0.375f;
        float sx = ox * 0.25f - 0.375f;
        int iy0 = (int)floorf(sy), ix0 = (int)floorf(sx);
        float fy = sy - (float)iy0, fx = sx - (float)ix0;
        int ly = iy0 - cyb, lx = ix0 - cxb;      // 0..16
        const float* cp = s_cell + ly * 18 + lx;
        float v00 = cp[0],  v01 = cp[1];
        float v10 = cp[18], v11 = cp[19];
        float top = v00 + fx * (v01 - v00);
        float bot = v10 + fx * (v11 - v10);
        o[(size_t)oy * IMG_W + ox] = top + fy * (bot - top);
    }
}

// ---------------------------------------------------------------------------
extern "C" void kernel_launch(void* const* d_in, const int* in_sizes, int n_in,
                              void* d_out, int out_size)
{
    const float* img = (const float*)d_in[0];
    const float* f0  = (const float*)d_in[1];
    const float* f1  = (const float*)d_in[2];
    const float* f2  = (const float*)d_in[3];
    float* out = (float*)d_out;

    nsst_prep<<<(3 * SLOTS * 32 + 255) / 256, 256>>>(f0, f1, f2);

    dim3 grid(4, 64, 12);
    nsst_mma_conv<<<grid, 256>>>(img, out);

    dim3 lgrid(8, 8, 12);
    nsst_lowpass<<<lgrid, 256>>>(img, out);
}

// round 13
// speedup vs baseline: 1.6226x; 1.6226x over previous
#include <cuda_runtime.h>
#include <cuda_fp16.h>
#include <cstdint>

// NSSTDecomposition via fp16 m16n8k16 mma.sync, per-scale implicit-GEMM split.
// s2: K=19x20(pad)=384, N=16 ; s1: K=15x16=240, N=8 ; s0: K=11x12->144, N=8.
// R13: R8 conv geometry (proven 262us: 4 rows/CTA, warp = 1 row x 64 px,
// grid 4x128x12), k-loops fully unrolled with R8's exact per-k addressing,
// + fused box4x4+bilinear lowpass kernel (verified in R12).

#define IMG_W   512
#define IMG_HW  (512*512)
#define WROWS   23             // 4 rows + 2*9 halo + K-pad overread (3+19=22 max)
#define WCOLS   152
#define WELEMS  (WROWS*WCOLS)  // 3496

// fragment slots per color: s2: 24g*2nt=48, s1: 15, s0: 9  => 72
#define SLOTS   72
#define SLOT_S1 48
#define SLOT_S0 63

__device__ uint2 g_bfrag[3*SLOTS*32];

__device__ __forceinline__ void mma_f16(float* d,
    uint32_t a0, uint32_t a1, uint32_t a2, uint32_t a3, uint32_t b0, uint32_t b1) {
    asm volatile("mma.sync.aligned.m16n8k16.row.col.f32.f16.f16.f32 "
                 "{%0,%1,%2,%3}, {%4,%5,%6,%7}, {%8,%9}, {%0,%1,%2,%3};"
                 : "+f"(d[0]), "+f"(d[1]), "+f"(d[2]), "+f"(d[3])
                 : "r"(a0), "r"(a1), "r"(a2), "r"(a3), "r"(b0), "r"(b1));
}

// ---------------------------------------------------------------------------
// Prep: weights -> f16 fragment image. Lane l of slot: n_row=l>>2, k pair base
// kq=(l&3)*2 ; b0 = {W[n][k0],W[n][k0+1]}, b1 = {W[n][k0+8],W[n][k0+9]}.
// ---------------------------------------------------------------------------
__global__ void __launch_bounds__(256)
nsst_prep(const float* __restrict__ f0, const float* __restrict__ f1,
          const float* __restrict__ f2)
{
    int i = blockIdx.x * 256 + threadIdx.x;          // 3*72*32 = 6912
    if (i >= 3 * SLOTS * 32) return;
    int l    = i & 31;
    int slot = (i >> 5) % SLOTS;
    int c    = i / (SLOTS * 32);
    int nr   = l >> 2;
    int kq   = (l & 3) * 2;

    uint32_t pk[2];
    #pragma unroll
    for (int r = 0; r < 2; r++) {
        int g, k;
        float v0 = 0.0f, v1 = 0.0f;
        if (slot < SLOT_S1) {                         // scale2: 19x19, PADW=20
            g = slot >> 1;
            int nt = slot & 1, nl = nt * 8 + nr;
            k = g * 16 + kq + r * 8;
            int dy = k / 20, dx = k - dy * 20;
            if (dy < 19 && nl < 16) {
                const float* fp = f2 + (size_t)(c * 16 + nl) * 361 + dy * 19 + dx;
                if (dx < 19)     v0 = fp[0];
                if (dx + 1 < 19) v1 = fp[1];
            }
        } else if (slot < SLOT_S0) {                  // scale1: 15x15, PADW=16
            g = slot - SLOT_S1;
            k = g * 16 + kq + r * 8;
            int dy = k >> 4, dx = k & 15;
            const float* fp = f1 + (size_t)(c * 8 + nr) * 225 + dy * 15 + dx;
            if (dx < 15)     v0 = fp[0];
            if (dx + 1 < 15) v1 = fp[1];
        } else {                                      // scale0: 11x11, PADW=12
            g = slot - SLOT_S0;
            k = g * 16 + kq + r * 8;
            int dy = k / 12, dx = k - dy * 12;
            if (dy < 11 && nr < 4) {
                const float* fp = f0 + (size_t)(c * 4 + nr) * 121 + dy * 11 + dx;
                if (dx < 11)     v0 = fp[0];
                if (dx + 1 < 11) v1 = fp[1];
            }
        }
        __half2 hh = __halves2half2(__float2half_rn(v0), __float2half_rn(v1));
        pk[r] = *reinterpret_cast<uint32_t*>(&hh);
    }
    g_bfrag[i] = make_uint2(pk[0], pk[1]);
}

// ---------------------------------------------------------------------------
// One scale: NG groups of k16, NT n8-tiles, 4 m16-tiles per warp (64 px).
// Unrolled g-loop; per-k dy/dx kept EXACTLY as R8 (kq folded in before the
// division — required because a k16 group can straddle a PADW row boundary).
// ---------------------------------------------------------------------------
template<int PADW, int RS, int NT, int NG, int NREAL, int CH0>
__device__ __forceinline__ void run_scale(
    const uint2* __restrict__ sb, const char* __restrict__ abase,
    float* __restrict__ obase,          // out + chbase*HW + y*512
    int l, int row_w, int xoff, int x0)
{
    const int roff = 9 - RS;
    const int px   = l >> 2;
    const int kq   = (l & 3) * 2;
    const int ebase = (roff + row_w) * WCOLS + roff + xoff + px;

    float acc[4][NT][4];
    #pragma unroll
    for (int mt = 0; mt < 4; mt++)
        #pragma unroll
        for (int nt = 0; nt < NT; nt++)
            #pragma unroll
            for (int q = 0; q < 4; q++) acc[mt][nt][q] = 0.0f;

    #pragma unroll
    for (int g = 0; g < NG; g++) {
        int k0 = g * 16 + kq;
        int k1 = k0 + 8;
        int dy0 = k0 / PADW, dx0 = k0 - dy0 * PADW;
        int dy1 = k1 / PADW, dx1 = k1 - dy1 * PADW;
        int e0 = ebase + dy0 * WCOLS + dx0;
        int e1 = ebase + dy1 * WCOLS + dx1;

        uint2 bf[NT];
        #pragma unroll
        for (int nt = 0; nt < NT; nt++) bf[nt] = sb[(g * NT + nt) * 32 + l];

        #pragma unroll
        for (int mt = 0; mt < 4; mt++) {
            uint32_t a0 = *(const uint32_t*)(abase + (size_t)(e0 + mt * 16) * 2);
            uint32_t a1 = *(const uint32_t*)(abase + (size_t)(e0 + mt * 16 + 8) * 2);
            uint32_t a2 = *(const uint32_t*)(abase + (size_t)(e1 + mt * 16) * 2);
            uint32_t a3 = *(const uint32_t*)(abase + (size_t)(e1 + mt * 16 + 8) * 2);
            #pragma unroll
            for (int nt = 0; nt < NT; nt++)
                mma_f16(acc[mt][nt], a0, a1, a2, a3, bf[nt].x, bf[nt].y);
        }
    }

    const int n2 = kq;                    // (l&3)*2
    #pragma unroll
    for (int mt = 0; mt < 4; mt++) {
        int x = xoff + mt * 16 + px + x0;
        #pragma unroll
        for (int nt = 0; nt < NT; nt++) {
            int n = nt * 8 + n2;
            if (n < NREAL) {
                float* o = obase + (size_t)(CH0 + n) * IMG_HW;
                o[x]              = acc[mt][nt][0];
                o[IMG_HW + x]     = acc[mt][nt][1];
                o[x + 8]          = acc[mt][nt][2];
                o[IMG_HW + x + 8] = acc[mt][nt][3];
            }
        }
    }
}

// ---------------------------------------------------------------------------
// Conv: grid (4 x-tiles, 128 y-quads, 12 bc), 256 threads = 8 warps.
// Warp w: y-row = w>>1, x-half = (w&1)*64.
// ---------------------------------------------------------------------------
__global__ void __launch_bounds__(256)
nsst_mma_conv(const float* __restrict__ img, float* __restrict__ out)
{
    __shared__ uint2 s_b[SLOTS * 32];                         // 18432 B
    __shared__ __align__(16) __half s_winA[WELEMS];           //  6992 B
    __shared__ __align__(16) __half s_winB[WELEMS];           //  6992 B (shift-1)

    const int tid = threadIdx.x;
    const int l   = tid & 31;
    const int w   = tid >> 5;
    const int x0  = blockIdx.x * 128;
    const int y0  = blockIdx.y * 4;
    const int bz  = blockIdx.z, b = bz / 3, c = bz % 3;

    // stage B fragments
    {
        const uint2* src = g_bfrag + (size_t)c * SLOTS * 32;
        for (int i = tid; i < SLOTS * 32; i += 256) s_b[i] = src[i];
    }
    // stage window (f16) + shifted copy, zero-padded
    {
        const float* src = img + (size_t)bz * IMG_HW;
        for (int i = tid; i < WELEMS; i += 256) {
            int iy = i / WCOLS, ix = i - iy * WCOLS;
            int gy = y0 + iy - 9, gx = x0 + ix - 9;
            float v = 0.0f;
            if ((unsigned)gy < 512u && (unsigned)gx < 512u) v = src[gy * IMG_W + gx];
            __half h = __float2half_rn(v);
            s_winA[i] = h;
            if (i > 0) s_winB[i - 1] = h;
        }
        if (tid == 0) s_winB[WELEMS - 1] = __float2half_rn(0.0f);
    }
    __syncthreads();

    const int row_w = w >> 1;
    const int xoff  = (w & 1) * 64;
    const char* abase = ((l >> 2) & 1) ? ((const char*)s_winB - 2)
                                       : (const char*)s_winA;
    float* obase = out + (size_t)(b * 87 + c * 29) * IMG_HW
                       + (size_t)(y0 + row_w) * IMG_W;

    run_scale<20, 9, 2, 24, 16, 12>(s_b,                abase, obase, l, row_w, xoff, x0);
    run_scale<16, 7, 1, 15,  8,  4>(s_b + SLOT_S1 * 32, abase, obase, l, row_w, xoff, x0);
    run_scale<12, 5, 1,  9,  4,  0>(s_b + SLOT_S0 * 32, abase, obase, l, row_w, xoff, x0);
}

// ---------------------------------------------------------------------------
// Fused lowpass: 4x4 box mean + bilinear upsample (clamp == jax renorm edge).
// Block = 64x64 output region; 18x18 lowpass cells in smem. (verified R12)
// ---------------------------------------------------------------------------
__global__ void __launch_bounds__(256)
nsst_lowpass(const float* __restrict__ img, float* __restrict__ out)
{
    __shared__ float s_cell[18 * 18];
    const int tid = threadIdx.x;
    const int x0 = blockIdx.x * 64;
    const int y0 = blockIdx.y * 64;
    const int bz = blockIdx.z, b = bz / 3, c = bz % 3;
    const int cyb = (y0 >> 2) - 1;
    const int cxb = (x0 >> 2) - 1;
    const float* src = img + (size_t)bz * IMG_HW;

    for (int i = tid; i < 324; i += 256) {
        int cy = min(127, max(0, cyb + i / 18));
        int cx = min(127, max(0, cxb + i % 18));
        const float* p = src + (size_t)(cy * 4) * IMG_W + cx * 4;
        float s = 0.0f;
        #pragma unroll
        for (int r = 0; r < 4; r++) {
            float4 v = *reinterpret_cast<const float4*>(p + r * IMG_W);
            s += v.x + v.y + v.z + v.w;
        }
        s_cell[i] = s * (1.0f / 16.0f);
    }
    __syncthreads();

    float* o = out + (size_t)(b * 87 + c * 29 + 28) * IMG_HW;
    #pragma unroll
    for (int j = 0; j < 16; j++) {
        int idx = tid + j * 256;                 // 0..4095
        int oy = y0 + (idx >> 6);
        int ox = x0 + (idx & 63);
        float sy = oy * 0.25f - 0.375f;
        float sx = ox * 0.25f - 0.375f;
        int iy0 = (int)floorf(sy), ix0 = (int)floorf(sx);
        float fy = sy - (float)iy0, fx = sx - (float)ix0;
        int ly = iy0 - cyb, lx = ix0 - cxb;      // 0..16
        const float* cp = s_cell + ly * 18 + lx;
        float v00 = cp[0],  v01 = cp[1];
        float v10 = cp[18], v11 = cp[19];
        float top = v00 + fx * (v01 - v00);
        float bot = v10 + fx * (v11 - v10);
        o[(size_t)oy * IMG_W + ox] = top + fy * (bot - top);
    }
}

// ---------------------------------------------------------------------------
extern "C" void kernel_launch(void* const* d_in, const int* in_sizes, int n_in,
                              void* d_out, int out_size)
{
    const float* img = (const float*)d_in[0];
    const float* f0  = (const float*)d_in[1];
    const float* f1  = (const float*)d_in[2];
    const float* f2  = (const float*)d_in[3];
    float* out = (float*)d_out;

    nsst_prep<<<(3 * SLOTS * 32 + 255) / 256, 256>>>(f0, f1, f2);

    dim3 grid(4, 128, 12);
    nsst_mma_conv<<<grid, 256>>>(img, out);

    dim3 lgrid(8, 8, 12);
    nsst_lowpass<<<lgrid, 256>>>(img, out);
}